// round 7
// baseline (speedup 1.0000x reference)
#include <cuda_runtime.h>
#include <cstdint>

#define NUM_T   128
#define DIM     1024
#define D4      (DIM / 4)
#define NC      512
#define TOPK    8
#define VPC     256
#define VOCAB   131072
#define TILE    8

// scratch (__device__ globals; no allocations allowed)
__device__ float g_scores[NUM_T * NC];
__device__ int   g_topk[NUM_T * TOPK];
__device__ int   g_cnt[NC];
__device__ int   g_toklist[NC * NUM_T];

// ---------------------------------------------------------------------------
// Centroid scores (block = 4 tokens x 128 centroids; grid (32,4) = 128 blocks)
// FUSED with output fill: each block also fills a 512-KB slice of the output
// with -FLT_MAX. Fill and scores are independent; interleaving hides the
// score GEMM behind the fill's store stream.
// ---------------------------------------------------------------------------
__global__ void scores_fill_kernel(const float* __restrict__ H,
                                   const float* __restrict__ C,
                                   float4* __restrict__ out, int n4) {
    __shared__ float4 Hs4[4 * D4];

    const int tid  = threadIdx.x;
    const int lane = tid & 31;
    const int warp = tid >> 5;
    const int t0   = blockIdx.x * 4;
    const int c0   = blockIdx.y * 128;

    const float4* H4 = (const float4*)H;
    for (int i = tid; i < 4 * D4; i += 256)
        Hs4[i] = H4[t0 * D4 + i];
    __syncthreads();

    const float4* C4 = (const float4*)C;
    for (int c = c0 + warp; c < c0 + 128; c += 8) {
        float a0 = 0.f, a1 = 0.f, a2 = 0.f, a3 = 0.f;
        #pragma unroll
        for (int j = 0; j < DIM / 128; j++) {
            const float4 cv = C4[(size_t)c * D4 + lane + 32 * j];
            const float4 h0 = Hs4[0 * D4 + lane + 32 * j];
            const float4 h1 = Hs4[1 * D4 + lane + 32 * j];
            const float4 h2 = Hs4[2 * D4 + lane + 32 * j];
            const float4 h3 = Hs4[3 * D4 + lane + 32 * j];
            a0 += cv.x * h0.x + cv.y * h0.y + cv.z * h0.z + cv.w * h0.w;
            a1 += cv.x * h1.x + cv.y * h1.y + cv.z * h1.z + cv.w * h1.w;
            a2 += cv.x * h2.x + cv.y * h2.y + cv.z * h2.z + cv.w * h2.w;
            a3 += cv.x * h3.x + cv.y * h3.y + cv.z * h3.z + cv.w * h3.w;
        }
        #pragma unroll
        for (int s = 16; s; s >>= 1) {
            a0 += __shfl_xor_sync(0xffffffffu, a0, s);
            a1 += __shfl_xor_sync(0xffffffffu, a1, s);
            a2 += __shfl_xor_sync(0xffffffffu, a2, s);
            a3 += __shfl_xor_sync(0xffffffffu, a3, s);
        }
        if (lane == 0) {
            g_scores[(t0 + 0) * NC + c] = a0;
            g_scores[(t0 + 1) * NC + c] = a1;
            g_scores[(t0 + 2) * NC + c] = a2;
            g_scores[(t0 + 3) * NC + c] = a3;
        }
    }

    // grid-stride fill of the output (-FLT_MAX) using all 128 blocks
    const float v = __int_as_float(0xff7fffff);
    const float4 f = make_float4(v, v, v, v);
    const int nblk    = gridDim.x * gridDim.y;
    const int blk     = blockIdx.y * gridDim.x + blockIdx.x;
    const int stride  = nblk * 256;
    for (int i = blk * 256 + tid; i < n4; i += stride)
        out[i] = f;
}

// ---------------------------------------------------------------------------
// Fused top-8 + inverted-index build. 1 block x 1024 threads.
// Warp w handles tokens 4w..4w+3. Tie-break: lowest index (lax.top_k).
// ---------------------------------------------------------------------------
__global__ void topk_build_kernel() {
    const int tid  = threadIdx.x;
    const int lane = tid & 31;
    const int warp = tid >> 5;
    const float NEG_INF = __int_as_float(0xff800000);

    for (int tt = 0; tt < 4; tt++) {
        const int t = warp * 4 + tt;
        float sc[16];
        #pragma unroll
        for (int j = 0; j < 16; j++)
            sc[j] = g_scores[t * NC + lane * 16 + j];

        #pragma unroll
        for (int r = 0; r < TOPK; r++) {
            float bv = sc[0];
            int   bi = lane * 16;
            #pragma unroll
            for (int j = 1; j < 16; j++)
                if (sc[j] > bv) { bv = sc[j]; bi = lane * 16 + j; }
            #pragma unroll
            for (int s = 16; s; s >>= 1) {
                const float ov = __shfl_xor_sync(0xffffffffu, bv, s);
                const int   oi = __shfl_xor_sync(0xffffffffu, bi, s);
                if (ov > bv || (ov == bv && oi < bi)) { bv = ov; bi = oi; }
            }
            if (lane == (bi >> 4)) sc[bi & 15] = NEG_INF;
            if (lane == 0) g_topk[t * TOPK + r] = bi;
        }
    }

    if (tid < NC) g_cnt[tid] = 0;
    __syncthreads();
    if (tid < NUM_T) {
        #pragma unroll
        for (int k = 0; k < TOPK; k++) {
            const int c   = g_topk[tid * TOPK + k];
            const int pos = atomicAdd(&g_cnt[c], 1);
            g_toklist[c * NUM_T + pos] = tid;
        }
    }
}

// ---------------------------------------------------------------------------
// Centroid-major logits + scatter. Block = (centroid, 64-row chunk).
// Each warp processes TWO rows per iteration (16 float4 loads in flight).
// Each W row is read exactly once from DRAM across the whole grid.
// ---------------------------------------------------------------------------
__global__ void __launch_bounds__(256) logits_kernel(
        const float* __restrict__ H,
        const float* __restrict__ W,
        const int* __restrict__ ord,
        float* __restrict__ out) {
    __shared__ float4 Hs[TILE][D4];   // 32 KB
    __shared__ int    toks[TILE];

    const int c     = blockIdx.x >> 2;
    const int chunk = blockIdx.x & 3;
    const int nt    = g_cnt[c];
    if (nt == 0) return;

    const int tid  = threadIdx.x;
    const int lane = tid & 31;
    const int warp = tid >> 5;
    const int r0   = chunk * 64;

    const float4* H4 = (const float4*)H;
    const float4* W4 = (const float4*)W;

    for (int base = 0; base < nt; base += TILE) {
        const int m = min(TILE, nt - base);
        if (tid < m) toks[tid] = g_toklist[c * NUM_T + base + tid];
        __syncthreads();
        for (int i = tid; i < m * D4; i += 256) {
            const int ti = i >> 8;
            const int e  = i & (D4 - 1);
            Hs[ti][e] = H4[(size_t)toks[ti] * D4 + e];
        }
        __syncthreads();

        #pragma unroll
        for (int rr = 0; rr < 64; rr += 16) {
            const int rA = r0 + rr + warp;
            const int rB = rA + 8;
            const int vidA = __ldg(&ord[c * VPC + rA]);
            const int vidB = __ldg(&ord[c * VPC + rB]);
            float4 wA[8], wB[8];
            #pragma unroll
            for (int j = 0; j < 8; j++) {
                wA[j] = W4[(size_t)vidA * D4 + lane + 32 * j];
                wB[j] = W4[(size_t)vidB * D4 + lane + 32 * j];
            }

            float pA[TILE], pB[TILE];
            #pragma unroll
            for (int i = 0; i < TILE; i++) {
                if (i < m) {
                    float sA = 0.f, sB = 0.f;
                    #pragma unroll
                    for (int j = 0; j < 8; j++) {
                        const float4 h = Hs[i][lane + 32 * j];
                        sA += wA[j].x * h.x + wA[j].y * h.y +
                              wA[j].z * h.z + wA[j].w * h.w;
                        sB += wB[j].x * h.x + wB[j].y * h.y +
                              wB[j].z * h.z + wB[j].w * h.w;
                    }
                    pA[i] = sA; pB[i] = sB;
                }
            }
            #pragma unroll
            for (int i = 0; i < TILE; i++) {
                if (i < m) {
                    float sA = pA[i], sB = pB[i];
                    #pragma unroll
                    for (int sft = 16; sft; sft >>= 1) {
                        sA += __shfl_xor_sync(0xffffffffu, sA, sft);
                        sB += __shfl_xor_sync(0xffffffffu, sB, sft);
                    }
                    if (lane == 0) {
                        out[(size_t)toks[i] * VOCAB + vidA] = sA;
                        out[(size_t)toks[i] * VOCAB + vidB] = sB;
                    }
                }
            }
        }
        __syncthreads();
    }
}

// ---------------------------------------------------------------------------
extern "C" void kernel_launch(void* const* d_in, const int* in_sizes, int n_in,
                              void* d_out, int out_size) {
    const float* H   = (const float*)d_in[0];   // (128, 1024)
    const float* W   = (const float*)d_in[1];   // (131072, 1024)
    const float* C   = (const float*)d_in[2];   // (512, 1024)
    const int*   ord = (const int*)d_in[3];     // (131072,)
    float* out = (float*)d_out;

    const int n4 = out_size / 4;
    scores_fill_kernel<<<dim3(NUM_T / 4, NC / 128), 256>>>(H, C, (float4*)out, n4);
    topk_build_kernel<<<1, 1024>>>();
    logits_kernel<<<NC * 4, 256>>>(H, W, ord, out);
}

// round 10
// speedup vs baseline: 1.1707x; 1.1707x over previous
#include <cuda_runtime.h>
#include <cstdint>

#define NUM_T   128
#define DIM     1024
#define D4      (DIM / 4)
#define NC      512
#define TOPK    8
#define VPC     256
#define VOCAB   131072
#define TILE    8

// scratch (__device__ globals; no allocations allowed)
__device__ float g_scores[NUM_T * NC];
__device__ int   g_topk[NUM_T * TOPK];
__device__ int   g_cnt[NC];
__device__ int   g_toklist[NC * NUM_T];

// ---------------------------------------------------------------------------
// Fill output with -FLT_MAX (jnp.finfo(float32).min)
// ---------------------------------------------------------------------------
__global__ void fill_kernel(float4* __restrict__ out, int n4) {
    const float v = __int_as_float(0xff7fffff);  // -FLT_MAX
    const float4 f = make_float4(v, v, v, v);
    for (int i = blockIdx.x * blockDim.x + threadIdx.x; i < n4;
         i += gridDim.x * blockDim.x)
        out[i] = f;
}

// ---------------------------------------------------------------------------
// Centroid scores: block = 4 tokens x 128 centroids. grid (32, 4).
// ---------------------------------------------------------------------------
__global__ void scores_kernel(const float* __restrict__ H,
                              const float* __restrict__ C) {
    __shared__ float4 Hs4[4 * D4];

    const int tid  = threadIdx.x;
    const int lane = tid & 31;
    const int warp = tid >> 5;
    const int t0   = blockIdx.x * 4;
    const int c0   = blockIdx.y * 128;

    const float4* H4 = (const float4*)H;
    for (int i = tid; i < 4 * D4; i += 256)
        Hs4[i] = H4[t0 * D4 + i];
    __syncthreads();

    const float4* C4 = (const float4*)C;
    for (int c = c0 + warp; c < c0 + 128; c += 8) {
        float a0 = 0.f, a1 = 0.f, a2 = 0.f, a3 = 0.f;
        #pragma unroll
        for (int j = 0; j < DIM / 128; j++) {
            const float4 cv = C4[(size_t)c * D4 + lane + 32 * j];
            const float4 h0 = Hs4[0 * D4 + lane + 32 * j];
            const float4 h1 = Hs4[1 * D4 + lane + 32 * j];
            const float4 h2 = Hs4[2 * D4 + lane + 32 * j];
            const float4 h3 = Hs4[3 * D4 + lane + 32 * j];
            a0 += cv.x * h0.x + cv.y * h0.y + cv.z * h0.z + cv.w * h0.w;
            a1 += cv.x * h1.x + cv.y * h1.y + cv.z * h1.z + cv.w * h1.w;
            a2 += cv.x * h2.x + cv.y * h2.y + cv.z * h2.z + cv.w * h2.w;
            a3 += cv.x * h3.x + cv.y * h3.y + cv.z * h3.z + cv.w * h3.w;
        }
        #pragma unroll
        for (int s = 16; s; s >>= 1) {
            a0 += __shfl_xor_sync(0xffffffffu, a0, s);
            a1 += __shfl_xor_sync(0xffffffffu, a1, s);
            a2 += __shfl_xor_sync(0xffffffffu, a2, s);
            a3 += __shfl_xor_sync(0xffffffffu, a3, s);
        }
        if (lane == 0) {
            g_scores[(t0 + 0) * NC + c] = a0;
            g_scores[(t0 + 1) * NC + c] = a1;
            g_scores[(t0 + 2) * NC + c] = a2;
            g_scores[(t0 + 3) * NC + c] = a3;
        }
    }
}

// ---------------------------------------------------------------------------
// Fused top-8 + inverted-index build. 1 block x 1024 threads.
// Warp w handles tokens 4w..4w+3. Tie-break: lowest index (lax.top_k).
// ---------------------------------------------------------------------------
__global__ void topk_build_kernel() {
    const int tid  = threadIdx.x;
    const int lane = tid & 31;
    const int warp = tid >> 5;
    const float NEG_INF = __int_as_float(0xff800000);

    for (int tt = 0; tt < 4; tt++) {
        const int t = warp * 4 + tt;
        float sc[16];
        #pragma unroll
        for (int j = 0; j < 16; j++)
            sc[j] = g_scores[t * NC + lane * 16 + j];

        #pragma unroll
        for (int r = 0; r < TOPK; r++) {
            float bv = sc[0];
            int   bi = lane * 16;
            #pragma unroll
            for (int j = 1; j < 16; j++)
                if (sc[j] > bv) { bv = sc[j]; bi = lane * 16 + j; }
            #pragma unroll
            for (int s = 16; s; s >>= 1) {
                const float ov = __shfl_xor_sync(0xffffffffu, bv, s);
                const int   oi = __shfl_xor_sync(0xffffffffu, bi, s);
                if (ov > bv || (ov == bv && oi < bi)) { bv = ov; bi = oi; }
            }
            if (lane == (bi >> 4)) sc[bi & 15] = NEG_INF;
            if (lane == 0) g_topk[t * TOPK + r] = bi;
        }
    }

    if (tid < NC) g_cnt[tid] = 0;
    __syncthreads();
    if (tid < NUM_T) {
        #pragma unroll
        for (int k = 0; k < TOPK; k++) {
            const int c   = g_topk[tid * TOPK + k];
            const int pos = atomicAdd(&g_cnt[c], 1);
            g_toklist[c * NUM_T + pos] = tid;
        }
    }
}

// ---------------------------------------------------------------------------
// Centroid-major logits + scatter (R4 version — measured ~100us).
// Block = (centroid, 64-row chunk). grid = 2048, 256 threads, warp per row.
// Each W row is read exactly once from DRAM across the whole grid.
// ---------------------------------------------------------------------------
__global__ void logits_kernel(const float* __restrict__ H,
                              const float* __restrict__ W,
                              const int* __restrict__ ord,
                              float* __restrict__ out) {
    __shared__ float4 Hs[TILE][D4];   // 32 KB
    __shared__ int    toks[TILE];

    const int c     = blockIdx.x >> 2;
    const int chunk = blockIdx.x & 3;
    const int nt    = g_cnt[c];
    if (nt == 0) return;

    const int tid  = threadIdx.x;
    const int lane = tid & 31;
    const int warp = tid >> 5;
    const int r0   = chunk * 64;

    const float4* H4 = (const float4*)H;
    const float4* W4 = (const float4*)W;

    for (int base = 0; base < nt; base += TILE) {
        const int m = min(TILE, nt - base);
        if (tid < m) toks[tid] = g_toklist[c * NUM_T + base + tid];
        __syncthreads();
        for (int i = tid; i < m * D4; i += 256) {
            const int ti = i >> 8;
            const int e  = i & (D4 - 1);
            Hs[ti][e] = H4[(size_t)toks[ti] * D4 + e];
        }
        __syncthreads();

        for (int r = r0 + warp; r < r0 + 64; r += 8) {
            const int vid = __ldg(&ord[c * VPC + r]);
            float4 w[8];
            #pragma unroll
            for (int j = 0; j < 8; j++)
                w[j] = W4[(size_t)vid * D4 + lane + 32 * j];

            for (int i = 0; i < m; i++) {
                float s = 0.f;
                #pragma unroll
                for (int j = 0; j < 8; j++) {
                    const float4 h = Hs[i][lane + 32 * j];
                    s += w[j].x * h.x + w[j].y * h.y +
                         w[j].z * h.z + w[j].w * h.w;
                }
                #pragma unroll
                for (int sft = 16; sft; sft >>= 1)
                    s += __shfl_xor_sync(0xffffffffu, s, sft);
                if (lane == 0)
                    out[(size_t)toks[i] * VOCAB + vid] = s;
            }
        }
        __syncthreads();
    }
}

// ---------------------------------------------------------------------------
extern "C" void kernel_launch(void* const* d_in, const int* in_sizes, int n_in,
                              void* d_out, int out_size) {
    const float* H   = (const float*)d_in[0];   // (128, 1024)
    const float* W   = (const float*)d_in[1];   // (131072, 1024)
    const float* C   = (const float*)d_in[2];   // (512, 1024)
    const int*   ord = (const int*)d_in[3];     // (131072,)
    float* out = (float*)d_out;

    const int n4 = out_size / 4;
    fill_kernel<<<2048, 256>>>((float4*)out, n4);
    scores_kernel<<<dim3(NUM_T / 4, NC / 128), 256>>>(H, C);
    topk_build_kernel<<<1, 1024>>>();
    logits_kernel<<<NC * 4, 256>>>(H, W, ord, out);
}

// round 11
// speedup vs baseline: 1.2590x; 1.0754x over previous
#include <cuda_runtime.h>
#include <cstdint>

#define NUM_T   128
#define DIM     1024
#define D4      (DIM / 4)
#define NC      512
#define TOPK    8
#define VPC     256
#define VOCAB   131072
#define TILE    4
#define RPC     32          // rows per chunk in fused kernel
#define NCHUNK  (VPC / RPC) // 8

// scratch (__device__ globals; no allocations allowed)
__device__ float g_scores[NUM_T * NC];
__device__ int   g_topk[NUM_T * TOPK];
__device__ int   g_cnt[NC];
__device__ int   g_toklist[NC * NUM_T];

// ---------------------------------------------------------------------------
// Centroid scores: block = 4 tokens x 128 centroids. grid (32, 4).
// ---------------------------------------------------------------------------
__global__ void scores_kernel(const float* __restrict__ H,
                              const float* __restrict__ C) {
    __shared__ float4 Hs4[4 * D4];

    const int tid  = threadIdx.x;
    const int lane = tid & 31;
    const int warp = tid >> 5;
    const int t0   = blockIdx.x * 4;
    const int c0   = blockIdx.y * 128;

    const float4* H4 = (const float4*)H;
    for (int i = tid; i < 4 * D4; i += 256)
        Hs4[i] = H4[t0 * D4 + i];
    __syncthreads();

    const float4* C4 = (const float4*)C;
    for (int c = c0 + warp; c < c0 + 128; c += 8) {
        float a0 = 0.f, a1 = 0.f, a2 = 0.f, a3 = 0.f;
        #pragma unroll
        for (int j = 0; j < DIM / 128; j++) {
            const float4 cv = C4[(size_t)c * D4 + lane + 32 * j];
            const float4 h0 = Hs4[0 * D4 + lane + 32 * j];
            const float4 h1 = Hs4[1 * D4 + lane + 32 * j];
            const float4 h2 = Hs4[2 * D4 + lane + 32 * j];
            const float4 h3 = Hs4[3 * D4 + lane + 32 * j];
            a0 += cv.x * h0.x + cv.y * h0.y + cv.z * h0.z + cv.w * h0.w;
            a1 += cv.x * h1.x + cv.y * h1.y + cv.z * h1.z + cv.w * h1.w;
            a2 += cv.x * h2.x + cv.y * h2.y + cv.z * h2.z + cv.w * h2.w;
            a3 += cv.x * h3.x + cv.y * h3.y + cv.z * h3.z + cv.w * h3.w;
        }
        #pragma unroll
        for (int s = 16; s; s >>= 1) {
            a0 += __shfl_xor_sync(0xffffffffu, a0, s);
            a1 += __shfl_xor_sync(0xffffffffu, a1, s);
            a2 += __shfl_xor_sync(0xffffffffu, a2, s);
            a3 += __shfl_xor_sync(0xffffffffu, a3, s);
        }
        if (lane == 0) {
            g_scores[(t0 + 0) * NC + c] = a0;
            g_scores[(t0 + 1) * NC + c] = a1;
            g_scores[(t0 + 2) * NC + c] = a2;
            g_scores[(t0 + 3) * NC + c] = a3;
        }
    }
}

// ---------------------------------------------------------------------------
// Fused top-8 + inverted-index build. 1 block x 1024 threads.
// Warp w handles tokens 4w..4w+3. Tie-break: lowest index (lax.top_k).
// ---------------------------------------------------------------------------
__global__ void topk_build_kernel() {
    const int tid  = threadIdx.x;
    const int lane = tid & 31;
    const int warp = tid >> 5;
    const float NEG_INF = __int_as_float(0xff800000);

    for (int tt = 0; tt < 4; tt++) {
        const int t = warp * 4 + tt;
        float sc[16];
        #pragma unroll
        for (int j = 0; j < 16; j++)
            sc[j] = g_scores[t * NC + lane * 16 + j];

        #pragma unroll
        for (int r = 0; r < TOPK; r++) {
            float bv = sc[0];
            int   bi = lane * 16;
            #pragma unroll
            for (int j = 1; j < 16; j++)
                if (sc[j] > bv) { bv = sc[j]; bi = lane * 16 + j; }
            #pragma unroll
            for (int s = 16; s; s >>= 1) {
                const float ov = __shfl_xor_sync(0xffffffffu, bv, s);
                const int   oi = __shfl_xor_sync(0xffffffffu, bi, s);
                if (ov > bv || (ov == bv && oi < bi)) { bv = ov; bi = oi; }
            }
            if (lane == (bi >> 4)) sc[bi & 15] = NEG_INF;
            if (lane == 0) g_topk[t * TOPK + r] = bi;
        }
    }

    if (tid < NC) g_cnt[tid] = 0;
    __syncthreads();
    if (tid < NUM_T) {
        #pragma unroll
        for (int k = 0; k < TOPK; k++) {
            const int c   = g_topk[tid * TOPK + k];
            const int pos = atomicAdd(&g_cnt[c], 1);
            g_toklist[c * NUM_T + pos] = tid;
        }
    }
}

// ---------------------------------------------------------------------------
// FUSED fill + centroid-major logits + scatter.
// Block = (centroid c, 32-row chunk). grid = 512*8 = 4096 blocks, 256 thr.
// The block exclusively OWNS output columns ord[c*256+r0 .. r0+32) for all
// 128 tokens: writes -FLT_MAX for tokens that did NOT select c (mask), and
// the computed logit for tokens that did. Every output position is written
// exactly once across the grid -> no ordering hazard, no separate fill pass,
// and the fill stores overlap the W-row loads.
// ---------------------------------------------------------------------------
__global__ void __launch_bounds__(256) logits_fill_kernel(
        const float* __restrict__ H,
        const float* __restrict__ W,
        const int* __restrict__ ord,
        float* __restrict__ out) {
    __shared__ float4   Hs[TILE][D4];    // 16 KB
    __shared__ int      toks[TILE];
    __shared__ uint32_t selmask[4];      // 128-bit token membership mask

    const int c     = blockIdx.x >> 3;
    const int chunk = blockIdx.x & 7;
    const int r0    = chunk * RPC;
    const int tid   = threadIdx.x;
    const int lane  = tid & 31;
    const int warp  = tid >> 5;
    const int nt    = g_cnt[c];

    if (tid < 4) selmask[tid] = 0;
    __syncthreads();
    if (tid < nt) {
        const int t = g_toklist[c * NUM_T + tid];
        atomicOr(&selmask[t >> 5], 1u << (t & 31));
    }
    __syncthreads();

    // ---- fill: -FLT_MAX for all non-selected tokens in owned columns ----
    // lane <-> row r0+lane; warp strides over tokens. For identity/contiguous
    // token_ordering these are fully coalesced 128B stores.
    const int vid = __ldg(&ord[c * VPC + r0 + lane]);
    const float NEGMAX = __int_as_float(0xff7fffff);  // -FLT_MAX
    const uint32_t m0 = selmask[0], m1 = selmask[1],
                   m2 = selmask[2], m3 = selmask[3];
    #pragma unroll
    for (int i = 0; i < NUM_T / 8; i++) {
        const int t = warp + i * 8;
        const uint32_t mw = (t < 32) ? m0 : (t < 64) ? m1 : (t < 96) ? m2 : m3;
        if (!((mw >> (t & 31)) & 1))
            out[(size_t)t * VOCAB + vid] = NEGMAX;
    }

    if (nt == 0) return;

    // ---- logits for tokens that selected c ----
    const float4* H4 = (const float4*)H;
    const float4* W4 = (const float4*)W;

    for (int base = 0; base < nt; base += TILE) {
        const int m = min(TILE, nt - base);
        if (tid < m) toks[tid] = g_toklist[c * NUM_T + base + tid];
        __syncthreads();
        for (int i = tid; i < m * D4; i += 256) {
            const int ti = i >> 8;
            const int e  = i & (D4 - 1);
            Hs[ti][e] = H4[(size_t)toks[ti] * D4 + e];
        }
        __syncthreads();

        #pragma unroll
        for (int rr = 0; rr < RPC; rr += 8) {
            const int r    = r0 + rr + warp;
            const int rvid = __ldg(&ord[c * VPC + r]);
            float4 w[8];
            #pragma unroll
            for (int j = 0; j < 8; j++)
                w[j] = W4[(size_t)rvid * D4 + lane + 32 * j];

            for (int i = 0; i < m; i++) {
                float s = 0.f;
                #pragma unroll
                for (int j = 0; j < 8; j++) {
                    const float4 h = Hs[i][lane + 32 * j];
                    s += w[j].x * h.x + w[j].y * h.y +
                         w[j].z * h.z + w[j].w * h.w;
                }
                #pragma unroll
                for (int sft = 16; sft; sft >>= 1)
                    s += __shfl_xor_sync(0xffffffffu, s, sft);
                if (lane == 0)
                    out[(size_t)toks[i] * VOCAB + rvid] = s;
            }
        }
        __syncthreads();
    }
}

// ---------------------------------------------------------------------------
extern "C" void kernel_launch(void* const* d_in, const int* in_sizes, int n_in,
                              void* d_out, int out_size) {
    const float* H   = (const float*)d_in[0];   // (128, 1024)
    const float* W   = (const float*)d_in[1];   // (131072, 1024)
    const float* C   = (const float*)d_in[2];   // (512, 1024)
    const int*   ord = (const int*)d_in[3];     // (131072,)
    float* out = (float*)d_out;

    scores_kernel<<<dim3(NUM_T / 4, NC / 128), 256>>>(H, C);
    topk_build_kernel<<<1, 1024>>>();
    logits_fill_kernel<<<NC * NCHUNK, 256>>>(H, W, ord, out);
}

// round 14
// speedup vs baseline: 1.3832x; 1.0987x over previous
#include <cuda_runtime.h>
#include <cstdint>

#define NUM_T   128
#define DIM     1024
#define D4      (DIM / 4)
#define NC      512
#define TOPK    8
#define VPC     256
#define VOCAB   131072
#define TILE    4
#define RPC     32          // rows per chunk in fused kernel
#define NCHUNK  (VPC / RPC) // 8

// scratch (__device__ globals; no allocations allowed)
__device__ float g_scores[NUM_T * NC];
__device__ int   g_topk[NUM_T * TOPK];

// ---------------------------------------------------------------------------
// Centroid scores: block = 4 tokens x 32 centroids. grid (32, 16) = 512 blk.
// Inner unroll capped at 2 to keep regs ~60 (R11 version hit 165 regs).
// ---------------------------------------------------------------------------
__global__ void scores_kernel(const float* __restrict__ H,
                              const float* __restrict__ C) {
    __shared__ float4 Hs4[4 * D4];   // 16 KB

    const int tid  = threadIdx.x;
    const int lane = tid & 31;
    const int warp = tid >> 5;
    const int t0   = blockIdx.x * 4;
    const int c0   = blockIdx.y * 32;

    const float4* H4 = (const float4*)H;
    for (int i = tid; i < 4 * D4; i += 256)
        Hs4[i] = H4[t0 * D4 + i];
    __syncthreads();

    const float4* C4 = (const float4*)C;
    for (int c = c0 + warp; c < c0 + 32; c += 8) {
        float a0 = 0.f, a1 = 0.f, a2 = 0.f, a3 = 0.f;
        #pragma unroll 2
        for (int j = 0; j < DIM / 128; j++) {
            const float4 cv = C4[(size_t)c * D4 + lane + 32 * j];
            const float4 h0 = Hs4[0 * D4 + lane + 32 * j];
            const float4 h1 = Hs4[1 * D4 + lane + 32 * j];
            const float4 h2 = Hs4[2 * D4 + lane + 32 * j];
            const float4 h3 = Hs4[3 * D4 + lane + 32 * j];
            a0 += cv.x * h0.x + cv.y * h0.y + cv.z * h0.z + cv.w * h0.w;
            a1 += cv.x * h1.x + cv.y * h1.y + cv.z * h1.z + cv.w * h1.w;
            a2 += cv.x * h2.x + cv.y * h2.y + cv.z * h2.z + cv.w * h2.w;
            a3 += cv.x * h3.x + cv.y * h3.y + cv.z * h3.z + cv.w * h3.w;
        }
        #pragma unroll
        for (int s = 16; s; s >>= 1) {
            a0 += __shfl_xor_sync(0xffffffffu, a0, s);
            a1 += __shfl_xor_sync(0xffffffffu, a1, s);
            a2 += __shfl_xor_sync(0xffffffffu, a2, s);
            a3 += __shfl_xor_sync(0xffffffffu, a3, s);
        }
        if (lane == 0) {
            g_scores[(t0 + 0) * NC + c] = a0;
            g_scores[(t0 + 1) * NC + c] = a1;
            g_scores[(t0 + 2) * NC + c] = a2;
            g_scores[(t0 + 3) * NC + c] = a3;
        }
    }
}

// ---------------------------------------------------------------------------
// Top-8 per token. 32 blocks x 128 threads, warp per token.
// Tie-break: lowest index (matches jax.lax.top_k). No index build here.
// ---------------------------------------------------------------------------
__global__ void topk_kernel() {
    const int t    = blockIdx.x * 4 + (threadIdx.x >> 5);
    const int lane = threadIdx.x & 31;
    const float NEG_INF = __int_as_float(0xff800000);

    float sc[16];
    #pragma unroll
    for (int j = 0; j < 16; j++)
        sc[j] = g_scores[t * NC + lane * 16 + j];

    #pragma unroll
    for (int r = 0; r < TOPK; r++) {
        float bv = sc[0];
        int   bi = lane * 16;
        #pragma unroll
        for (int j = 1; j < 16; j++)
            if (sc[j] > bv) { bv = sc[j]; bi = lane * 16 + j; }
        #pragma unroll
        for (int s = 16; s; s >>= 1) {
            const float ov = __shfl_xor_sync(0xffffffffu, bv, s);
            const int   oi = __shfl_xor_sync(0xffffffffu, bi, s);
            if (ov > bv || (ov == bv && oi < bi)) { bv = ov; bi = oi; }
        }
        if (lane == (bi >> 4)) sc[bi & 15] = NEG_INF;
        if (lane == 0) g_topk[t * TOPK + r] = bi;
    }
}

// ---------------------------------------------------------------------------
// FUSED fill + centroid-major logits + scatter.
// Block = (centroid c, 32-row chunk); grid = 4096, 256 threads.
// The block OWNS output columns ord[c*256+r0 .. +32) for all 128 tokens:
// -FLT_MAX for non-selecting tokens, logits for selecting ones. Each output
// position written exactly once across the grid. Token list + membership
// mask are rebuilt locally from g_topk (ballot, no global atomics).
// W-row loads split into two 4xfloat4 halves to keep regs ~45 -> 6 blk/SM.
// ---------------------------------------------------------------------------
__global__ void __launch_bounds__(256) logits_fill_kernel(
        const float* __restrict__ H,
        const float* __restrict__ W,
        const int* __restrict__ ord,
        float* __restrict__ out) {
    __shared__ float4   Hs[TILE][D4];    // 16 KB
    __shared__ int      toklist_s[NUM_T];
    __shared__ int      toks[TILE];
    __shared__ uint32_t selmask[4];
    __shared__ int      nt_s;

    const int c     = blockIdx.x >> 3;
    const int chunk = blockIdx.x & 7;
    const int r0    = chunk * RPC;
    const int tid   = threadIdx.x;
    const int lane  = tid & 31;
    const int warp  = tid >> 5;

    if (tid == 0) nt_s = 0;
    __syncthreads();

    if (tid < NUM_T) {
        bool sel = false;
        #pragma unroll
        for (int k = 0; k < TOPK; k++)
            sel |= (g_topk[tid * TOPK + k] == c);
        const uint32_t b = __ballot_sync(0xffffffffu, sel);
        if (lane == 0) selmask[warp] = b;
        if (sel) toklist_s[atomicAdd(&nt_s, 1)] = tid;
    }
    __syncthreads();
    const int nt = nt_s;

    // ---- fill: -FLT_MAX for all non-selected tokens in owned columns ----
    const int vid = __ldg(&ord[c * VPC + r0 + lane]);
    const float NEGMAX = __int_as_float(0xff7fffff);  // -FLT_MAX
    const uint32_t m0 = selmask[0], m1 = selmask[1],
                   m2 = selmask[2], m3 = selmask[3];
    #pragma unroll
    for (int i = 0; i < NUM_T / 8; i++) {
        const int t = warp + i * 8;
        const uint32_t mw = (t < 32) ? m0 : (t < 64) ? m1 : (t < 96) ? m2 : m3;
        if (!((mw >> (t & 31)) & 1))
            out[(size_t)t * VOCAB + vid] = NEGMAX;
    }

    if (nt == 0) return;

    // ---- logits for tokens that selected c ----
    const float4* H4 = (const float4*)H;
    const float4* W4 = (const float4*)W;

    for (int base = 0; base < nt; base += TILE) {
        const int m = min(TILE, nt - base);
        if (tid < m) toks[tid] = toklist_s[base + tid];
        __syncthreads();
        for (int i = tid; i < m * D4; i += 256) {
            const int ti = i >> 8;
            const int e  = i & (D4 - 1);
            Hs[ti][e] = H4[(size_t)toks[ti] * D4 + e];
        }
        __syncthreads();

        #pragma unroll
        for (int rr = 0; rr < RPC; rr += 8) {
            const int r    = r0 + rr + warp;
            const int rvid = __ldg(&ord[c * VPC + r]);
            float s0 = 0.f, s1 = 0.f, s2 = 0.f, s3 = 0.f;

            #pragma unroll
            for (int half = 0; half < 2; half++) {
                float4 w[4];
                #pragma unroll
                for (int j = 0; j < 4; j++)
                    w[j] = W4[(size_t)rvid * D4 + lane + 32 * (half * 4 + j)];
                #pragma unroll
                for (int j = 0; j < 4; j++) {
                    const int e = lane + 32 * (half * 4 + j);
                    {
                        const float4 h = Hs[0][e];
                        s0 += w[j].x * h.x + w[j].y * h.y + w[j].z * h.z + w[j].w * h.w;
                    }
                    if (m > 1) {
                        const float4 h = Hs[1][e];
                        s1 += w[j].x * h.x + w[j].y * h.y + w[j].z * h.z + w[j].w * h.w;
                    }
                    if (m > 2) {
                        const float4 h = Hs[2][e];
                        s2 += w[j].x * h.x + w[j].y * h.y + w[j].z * h.z + w[j].w * h.w;
                    }
                    if (m > 3) {
                        const float4 h = Hs[3][e];
                        s3 += w[j].x * h.x + w[j].y * h.y + w[j].z * h.z + w[j].w * h.w;
                    }
                }
            }

            #pragma unroll
            for (int sft = 16; sft; sft >>= 1) {
                s0 += __shfl_xor_sync(0xffffffffu, s0, sft);
                s1 += __shfl_xor_sync(0xffffffffu, s1, sft);
                s2 += __shfl_xor_sync(0xffffffffu, s2, sft);
                s3 += __shfl_xor_sync(0xffffffffu, s3, sft);
            }
            if (lane == 0) {
                out[(size_t)toks[0] * VOCAB + rvid] = s0;
                if (m > 1) out[(size_t)toks[1] * VOCAB + rvid] = s1;
                if (m > 2) out[(size_t)toks[2] * VOCAB + rvid] = s2;
                if (m > 3) out[(size_t)toks[3] * VOCAB + rvid] = s3;
            }
        }
        __syncthreads();
    }
}

// ---------------------------------------------------------------------------
extern "C" void kernel_launch(void* const* d_in, const int* in_sizes, int n_in,
                              void* d_out, int out_size) {
    const float* H   = (const float*)d_in[0];   // (128, 1024)
    const float* W   = (const float*)d_in[1];   // (131072, 1024)
    const float* C   = (const float*)d_in[2];   // (512, 1024)
    const int*   ord = (const int*)d_in[3];     // (131072,)
    float* out = (float*)d_out;

    scores_kernel<<<dim3(NUM_T / 4, NC / 32), 256>>>(H, C);
    topk_kernel<<<NUM_T / 4, 128>>>();
    logits_fill_kernel<<<NC * NCHUNK, 256>>>(H, W, ord, out);
}

// round 15
// speedup vs baseline: 1.5290x; 1.1054x over previous
#include <cuda_runtime.h>
#include <cstdint>

#define NUM_T   128
#define DIM     1024
#define D4      (DIM / 4)
#define NC      512
#define TOPK    8
#define VPC     256
#define VOCAB   131072
#define TILE    4
#define RPC     32          // rows per chunk in fused kernel
#define NCHUNK  (VPC / RPC) // 8

// scratch (__device__ globals; no allocations allowed)
__device__ float g_scores[NUM_T * NC];
__device__ int   g_topk[NUM_T * TOPK];

// ---------------------------------------------------------------------------
// Centroid scores: block = 4 tokens x 8 centroids (warp per centroid).
// grid (32, 64) = 2048 blocks -> full occupancy, latency hidden.
// ---------------------------------------------------------------------------
__global__ void scores_kernel(const float* __restrict__ H,
                              const float* __restrict__ C) {
    __shared__ float4 Hs4[4 * D4];   // 16 KB

    const int tid  = threadIdx.x;
    const int lane = tid & 31;
    const int warp = tid >> 5;
    const int t0   = blockIdx.x * 4;
    const int c    = blockIdx.y * 8 + warp;

    const float4* H4 = (const float4*)H;
    for (int i = tid; i < 4 * D4; i += 256)
        Hs4[i] = H4[t0 * D4 + i];
    __syncthreads();

    const float4* C4 = (const float4*)C;
    float a0 = 0.f, a1 = 0.f, a2 = 0.f, a3 = 0.f;
    #pragma unroll 2
    for (int j = 0; j < DIM / 128; j++) {
        const float4 cv = C4[(size_t)c * D4 + lane + 32 * j];
        const float4 h0 = Hs4[0 * D4 + lane + 32 * j];
        const float4 h1 = Hs4[1 * D4 + lane + 32 * j];
        const float4 h2 = Hs4[2 * D4 + lane + 32 * j];
        const float4 h3 = Hs4[3 * D4 + lane + 32 * j];
        a0 += cv.x * h0.x + cv.y * h0.y + cv.z * h0.z + cv.w * h0.w;
        a1 += cv.x * h1.x + cv.y * h1.y + cv.z * h1.z + cv.w * h1.w;
        a2 += cv.x * h2.x + cv.y * h2.y + cv.z * h2.z + cv.w * h2.w;
        a3 += cv.x * h3.x + cv.y * h3.y + cv.z * h3.z + cv.w * h3.w;
    }
    #pragma unroll
    for (int s = 16; s; s >>= 1) {
        a0 += __shfl_xor_sync(0xffffffffu, a0, s);
        a1 += __shfl_xor_sync(0xffffffffu, a1, s);
        a2 += __shfl_xor_sync(0xffffffffu, a2, s);
        a3 += __shfl_xor_sync(0xffffffffu, a3, s);
    }
    if (lane == 0) {
        g_scores[(t0 + 0) * NC + c] = a0;
        g_scores[(t0 + 1) * NC + c] = a1;
        g_scores[(t0 + 2) * NC + c] = a2;
        g_scores[(t0 + 3) * NC + c] = a3;
    }
}

// ---------------------------------------------------------------------------
// Top-8 per token. 32 blocks x 128 threads, warp per token.
// Tie-break: lowest index (matches jax.lax.top_k).
// ---------------------------------------------------------------------------
__global__ void topk_kernel() {
    const int t    = blockIdx.x * 4 + (threadIdx.x >> 5);
    const int lane = threadIdx.x & 31;
    const float NEG_INF = __int_as_float(0xff800000);

    float sc[16];
    #pragma unroll
    for (int j = 0; j < 16; j++)
        sc[j] = g_scores[t * NC + lane * 16 + j];

    #pragma unroll
    for (int r = 0; r < TOPK; r++) {
        float bv = sc[0];
        int   bi = lane * 16;
        #pragma unroll
        for (int j = 1; j < 16; j++)
            if (sc[j] > bv) { bv = sc[j]; bi = lane * 16 + j; }
        #pragma unroll
        for (int s = 16; s; s >>= 1) {
            const float ov = __shfl_xor_sync(0xffffffffu, bv, s);
            const int   oi = __shfl_xor_sync(0xffffffffu, bi, s);
            if (ov > bv || (ov == bv && oi < bi)) { bv = ov; bi = oi; }
        }
        if (lane == (bi >> 4)) sc[bi & 15] = NEG_INF;
        if (lane == 0) g_topk[t * TOPK + r] = bi;
    }
}

// ---------------------------------------------------------------------------
// FUSED fill + centroid-major logits + scatter.
// Block = (centroid c, 32-row chunk); grid = 4096, 256 threads.
// Exclusive output ownership: -FLT_MAX for non-selecting tokens, logits for
// selecting ones; every position written exactly once across the grid.
// W rows: __ldcs (single-use, keep out of L2). Output: __stcs (write-once).
// ---------------------------------------------------------------------------
__global__ void __launch_bounds__(256) logits_fill_kernel(
        const float* __restrict__ H,
        const float* __restrict__ W,
        const int* __restrict__ ord,
        float* __restrict__ out) {
    __shared__ float4   Hs[TILE][D4];    // 16 KB
    __shared__ int      toklist_s[NUM_T];
    __shared__ int      toks[TILE];
    __shared__ uint32_t selmask[4];
    __shared__ int      nt_s;

    const int c     = blockIdx.x >> 3;
    const int chunk = blockIdx.x & 7;
    const int r0    = chunk * RPC;
    const int tid   = threadIdx.x;
    const int lane  = tid & 31;
    const int warp  = tid >> 5;

    if (tid == 0) nt_s = 0;
    __syncthreads();

    if (tid < NUM_T) {
        bool sel = false;
        #pragma unroll
        for (int k = 0; k < TOPK; k++)
            sel |= (g_topk[tid * TOPK + k] == c);
        const uint32_t b = __ballot_sync(0xffffffffu, sel);
        if (lane == 0) selmask[warp] = b;
        if (sel) toklist_s[atomicAdd(&nt_s, 1)] = tid;
    }
    __syncthreads();
    const int nt = nt_s;

    // ---- fill: -FLT_MAX for all non-selected tokens in owned columns ----
    const int vid = __ldg(&ord[c * VPC + r0 + lane]);
    const float NEGMAX = __int_as_float(0xff7fffff);  // -FLT_MAX
    const uint32_t m0 = selmask[0], m1 = selmask[1],
                   m2 = selmask[2], m3 = selmask[3];
    #pragma unroll
    for (int i = 0; i < NUM_T / 8; i++) {
        const int t = warp + i * 8;
        const uint32_t mw = (t < 32) ? m0 : (t < 64) ? m1 : (t < 96) ? m2 : m3;
        if (!((mw >> (t & 31)) & 1))
            __stcs(&out[(size_t)t * VOCAB + vid], NEGMAX);
    }

    if (nt == 0) return;

    // ---- logits for tokens that selected c ----
    const float4* H4 = (const float4*)H;
    const float4* W4 = (const float4*)W;

    for (int base = 0; base < nt; base += TILE) {
        const int m = min(TILE, nt - base);
        if (tid < m) toks[tid] = toklist_s[base + tid];
        __syncthreads();
        for (int i = tid; i < m * D4; i += 256) {
            const int ti = i >> 8;
            const int e  = i & (D4 - 1);
            Hs[ti][e] = H4[(size_t)toks[ti] * D4 + e];
        }
        __syncthreads();

        int rvid = __ldg(&ord[c * VPC + r0 + warp]);
        #pragma unroll
        for (int rr = 0; rr < RPC; rr += 8) {
            const int cur_vid = rvid;
            // prefetch next row's vocab id before the heavy work
            if (rr + 8 < RPC)
                rvid = __ldg(&ord[c * VPC + r0 + rr + 8 + warp]);

            float s0 = 0.f, s1 = 0.f, s2 = 0.f, s3 = 0.f;
            #pragma unroll
            for (int half = 0; half < 2; half++) {
                float4 w[4];
                #pragma unroll
                for (int j = 0; j < 4; j++)
                    w[j] = __ldcs(&W4[(size_t)cur_vid * D4 + lane + 32 * (half * 4 + j)]);
                #pragma unroll
                for (int j = 0; j < 4; j++) {
                    const int e = lane + 32 * (half * 4 + j);
                    {
                        const float4 h = Hs[0][e];
                        s0 += w[j].x * h.x + w[j].y * h.y + w[j].z * h.z + w[j].w * h.w;
                    }
                    if (m > 1) {
                        const float4 h = Hs[1][e];
                        s1 += w[j].x * h.x + w[j].y * h.y + w[j].z * h.z + w[j].w * h.w;
                    }
                    if (m > 2) {
                        const float4 h = Hs[2][e];
                        s2 += w[j].x * h.x + w[j].y * h.y + w[j].z * h.z + w[j].w * h.w;
                    }
                    if (m > 3) {
                        const float4 h = Hs[3][e];
                        s3 += w[j].x * h.x + w[j].y * h.y + w[j].z * h.z + w[j].w * h.w;
                    }
                }
            }

            #pragma unroll
            for (int sft = 16; sft; sft >>= 1) {
                s0 += __shfl_xor_sync(0xffffffffu, s0, sft);
                s1 += __shfl_xor_sync(0xffffffffu, s1, sft);
                s2 += __shfl_xor_sync(0xffffffffu, s2, sft);
                s3 += __shfl_xor_sync(0xffffffffu, s3, sft);
            }
            if (lane == 0) {
                __stcs(&out[(size_t)toks[0] * VOCAB + cur_vid], s0);
                if (m > 1) __stcs(&out[(size_t)toks[1] * VOCAB + cur_vid], s1);
                if (m > 2) __stcs(&out[(size_t)toks[2] * VOCAB + cur_vid], s2);
                if (m > 3) __stcs(&out[(size_t)toks[3] * VOCAB + cur_vid], s3);
            }
        }
        __syncthreads();
    }
}

// ---------------------------------------------------------------------------
extern "C" void kernel_launch(void* const* d_in, const int* in_sizes, int n_in,
                              void* d_out, int out_size) {
    const float* H   = (const float*)d_in[0];   // (128, 1024)
    const float* W   = (const float*)d_in[1];   // (131072, 1024)
    const float* C   = (const float*)d_in[2];   // (512, 1024)
    const int*   ord = (const int*)d_in[3];     // (131072,)
    float* out = (float*)d_out;

    scores_kernel<<<dim3(NUM_T / 4, NC / 8), 256>>>(H, C);
    topk_kernel<<<NUM_T / 4, 128>>>();
    logits_fill_kernel<<<NC * NCHUNK, 256>>>(H, W, ord, out);
}